// round 13
// baseline (speedup 1.0000x reference)
#include <cuda_runtime.h>
#include <cuda_fp16.h>
#include <math.h>
#include <stdint.h>

#define Hh 256
#define N2d 32
#define Bb 8
#define Ll 4096

typedef unsigned long long ull;

// -------- scratch (no allocations allowed) --------
__device__ float g_lam_re[Hh*N2d], g_lam_im[Hh*N2d];
__device__ float g_c_re[Hh*N2d],   g_c_im[Hh*N2d];
__device__ __align__(16) __half g_Wh[2*Hh*Hh];
// Y natural layout: [b][h][l]. single fp16 (post-GELU activations).
__device__ __align__(16) __half g_Yh[(size_t)Bb*Hh*Ll];

__device__ __forceinline__ uint32_t smem_u32(const void* p) {
    uint32_t a;
    asm("{ .reg .u64 t; cvta.to.shared.u64 t, %1; cvt.u32.u64 %0, t; }" : "=r"(a) : "l"(p));
    return a;
}
__device__ __forceinline__ void ldsm4(uint32_t* r, uint32_t a) {
    asm volatile("ldmatrix.sync.aligned.m8n8.x4.shared.b16 {%0,%1,%2,%3}, [%4];"
                 : "=r"(r[0]), "=r"(r[1]), "=r"(r[2]), "=r"(r[3]) : "r"(a));
}
__device__ __forceinline__ void ldsm4t(uint32_t* r, uint32_t a) {
    asm volatile("ldmatrix.sync.aligned.m8n8.x4.trans.shared.b16 {%0,%1,%2,%3}, [%4];"
                 : "=r"(r[0]), "=r"(r[1]), "=r"(r[2]), "=r"(r[3]) : "r"(a));
}
__device__ __forceinline__ void mma16816(float* c, const uint32_t* a,
                                         uint32_t b0, uint32_t b1) {
    asm volatile(
        "mma.sync.aligned.m16n8k16.row.col.f32.f16.f16.f32 "
        "{%0,%1,%2,%3}, {%4,%5,%6,%7}, {%8,%9}, {%0,%1,%2,%3};"
        : "+f"(c[0]), "+f"(c[1]), "+f"(c[2]), "+f"(c[3])
        : "r"(a[0]), "r"(a[1]), "r"(a[2]), "r"(a[3]), "r"(b0), "r"(b1));
}
__device__ __forceinline__ void cpa16(uint32_t dst, const void* src) {
    asm volatile("cp.async.cg.shared.global [%0], [%1], 16;" :: "r"(dst), "l"(src));
}
// ---- packed f32x2 helpers ----
__device__ __forceinline__ ull pk2f(float lo, float hi) {
    ull r; asm("mov.b64 %0, {%1,%2};" : "=l"(r) : "f"(lo), "f"(hi)); return r;
}
__device__ __forceinline__ void upk2f(ull v, float& lo, float& hi) {
    asm("mov.b64 {%0,%1}, %2;" : "=f"(lo), "=f"(hi) : "l"(v));
}
__device__ __forceinline__ ull mul2(ull a, ull b) {
    ull d; asm("mul.rn.f32x2 %0, %1, %2;" : "=l"(d) : "l"(a), "l"(b)); return d;
}
__device__ __forceinline__ ull fma2(ull a, ull b, ull c) {
    ull d; asm("fma.rn.f32x2 %0, %1, %2, %3;" : "=l"(d) : "l"(a), "l"(b), "l"(c)); return d;
}
__device__ __forceinline__ ull add2(ull a, ull b) {
    ull d; asm("add.rn.f32x2 %0, %1, %2;" : "=l"(d) : "l"(a), "l"(b)); return d;
}

// ============================================================
// Kernel 1a: discretization  lambda = exp(dt*A),  c = 2*C*(lambda-1)/A
// ============================================================
__global__ void prep_kernel(const float* __restrict__ log_dt,
                            const float* __restrict__ C,
                            const float* __restrict__ log_A_real,
                            const float* __restrict__ A_imag) {
    int idx = blockIdx.x*blockDim.x + threadIdx.x;
    if (idx >= Hh*N2d) return;
    int h = idx / N2d;
    float dt  = expf(log_dt[h]);
    float Are = -expf(log_A_real[idx]);
    float Aim = A_imag[idx];
    float dr = Are*dt, di = Aim*dt;
    float er = expf(dr);
    float lr = er*cosf(di), li = er*sinf(di);
    float e1r = lr - 1.0f, e1i = li;
    float den = Are*Are + Aim*Aim;
    float ir =  Are/den, ii = -Aim/den;
    float tr = e1r*ir - e1i*ii;
    float ti = e1r*ii + e1i*ir;
    float Cr = C[2*idx], Ci = C[2*idx+1];
    g_lam_re[idx] = lr;  g_lam_im[idx] = li;
    g_c_re[idx] = 2.0f*(Cr*tr - Ci*ti);
    g_c_im[idx] = 2.0f*(Cr*ti + Ci*tr);
}

// ============================================================
// Kernel 1b: W -> fp16
// ============================================================
__global__ void wsplit_kernel(const float* __restrict__ W) {
    int i = blockIdx.x*blockDim.x + threadIdx.x;
    if (i >= 2*Hh*Hh) return;
    g_Wh[i] = __float2half(W[i]);
}

// ============================================================
// Kernel 2: diagonal-SSM scan, TWO channels per warp packed in
// f32x2 lanes (component-wise separable across channels).
// warp = channel pair (2wp, 2wp+1); lane = mode n.
//   TRE' = LR2*TRE + NLI2*TIM + CR2*U2
//   TIM' = LR2*TIM +  LI2*TRE + CI2*U2
// tile[w][step][mode] holds packed (tre_a, tre_b); stride-33 ull
// rows are bank-conflict-free for STS.64 and the LDS.64 reads.
// ============================================================
__global__ void __launch_bounds__(128) scan_kernel(const float* __restrict__ u,
                                                   const float* __restrict__ D) {
    __shared__ ull tile[4][32][33];
    int w    = threadIdx.x >> 5;
    int lane = threadIdx.x & 31;
    int wp   = blockIdx.x*4 + w;          // 0..1023 (channel pair)
    int ch0  = wp*2;
    int b    = ch0 >> 8;
    int h0   = ch0 & 255;                  // even; h1 = h0+1 in same b
    const float* up0 = u + (size_t)(b*Hh + h0)*Ll;
    const float* up1 = up0 + Ll;
    __half* yh0 = g_Yh + (size_t)(b*Hh + h0)*Ll;
    __half* yh1 = yh0 + Ll;
    int ci0 = h0*N2d + lane, ci1 = ci0 + N2d;
    const ull LR2  = pk2f(g_lam_re[ci0],  g_lam_re[ci1]);
    const ull LI2  = pk2f(g_lam_im[ci0],  g_lam_im[ci1]);
    const ull NLI2 = pk2f(-g_lam_im[ci0], -g_lam_im[ci1]);
    const ull CR2  = pk2f(g_c_re[ci0],    g_c_re[ci1]);
    const ull CI2  = pk2f(g_c_im[ci0],    g_c_im[ci1]);
    float Dh0 = D[h0], Dh1 = D[h0+1];
    ull TRE = 0ULL, TIM = 0ULL;

    float uv0 = up0[lane], uv1 = up1[lane];   // block 0
    for (int ch = 0; ch < Ll/32; ++ch) {
        int nidx = (ch + 1 < Ll/32) ? (ch + 1)*32 : ch*32;
        float uv0n = up0[nidx + lane];
        float uv1n = up1[nidx + lane];
        #pragma unroll
        for (int i = 0; i < 32; ++i) {
            float u0 = __shfl_sync(0xffffffffu, uv0, i);
            float u1 = __shfl_sync(0xffffffffu, uv1, i);
            ull U2 = pk2f(u0, u1);
            ull Pr = mul2(CR2, U2);
            ull Pi = mul2(CI2, U2);
            ull nTRE = fma2(LR2, TRE, fma2(NLI2, TIM, Pr));
            ull nTIM = fma2(LR2, TIM, fma2(LI2,  TRE, Pi));
            TRE = nTRE; TIM = nTIM;
            tile[w][i][lane] = TRE;    // packed (tre_a, tre_b)
        }
        __syncwarp();
        // lane = output step: packed sum over 32 modes
        const ull* row = &tile[w][lane][0];
        ull s0 = 0ULL, s1 = 0ULL, s2 = 0ULL, s3 = 0ULL;
        #pragma unroll
        for (int j = 0; j < 32; j += 4) {
            s0 = add2(s0, row[j+0]);
            s1 = add2(s1, row[j+1]);
            s2 = add2(s2, row[j+2]);
            s3 = add2(s3, row[j+3]);
        }
        ull st = add2(add2(s0, s1), add2(s2, s3));
        float accA, accB; upk2f(st, accA, accB);
        float y0 = fmaf(Dh0, uv0, accA);
        float y1 = fmaf(Dh1, uv1, accB);
        float g0 = 0.5f*y0*(1.0f + erff(y0*0.70710678118654752f));
        float g1 = 0.5f*y1*(1.0f + erff(y1*0.70710678118654752f));
        yh0[ch*32 + lane] = __float2half(g0);
        yh1[ch*32 + lane] = __float2half(g1);
        uv0 = uv0n; uv1 = uv1n;
        __syncwarp();
    }
}

// ============================================================
// Kernel 3: HMMA.16816 fp16 GEMM + bias + GLU (R12, 50.7us).
// 512 threads, 128x128 tile, 3-stage cp.async.
// ============================================================
#define AROW 48
#define ABUF (128*AROW)
#define BROW 272
#define BBUF (16*BROW)
#define BOFF (2*ABUF)
#define STAGEB (2*ABUF + BBUF)
#define GEMM_SMEM (3*STAGEB)

__global__ void __launch_bounds__(512, 1) gemm_mma_kernel(const float* __restrict__ bias,
                                                          float* __restrict__ out) {
    extern __shared__ char smem[];
    const uint32_t sb = smem_u32(smem);

    const int tid  = threadIdx.x;
    const int lane = tid & 31;
    const int w    = tid >> 5;
    const int wm   = w >> 2;
    const int wn   = w & 3;
    const int l0 = blockIdx.x*128;
    const int h0 = blockIdx.y*128;
    const int b  = blockIdx.z;

    const int aarr = tid >> 8;
    const int arow = (tid & 255) >> 1, aseg = tid & 1;
    const __half* pA = g_Wh + (size_t)(aarr*Hh + h0 + arow)*Hh + aseg*8;
    const uint32_t aDst = (uint32_t)(aarr*ABUF + arow*AROW + aseg*16);
    const int brow = (tid >> 4) & 15, bch = tid & 15;
    const __half* pB = g_Yh + ((size_t)b*Hh + brow)*Ll + l0 + bch*8;
    const uint32_t bDst = (uint32_t)(BOFF + brow*BROW + bch*16);
    const bool doB = (tid < 256);

    const uint32_t a_off = (uint32_t)((lane & 15)*AROW + (lane >> 4)*16);
    const uint32_t b_off = (uint32_t)(((lane & 7) + ((lane >> 3) & 1)*8)*BROW
                                      + (lane >> 4)*16);

    float acc_a[2][4][4], acc_g[2][4][4];
    #pragma unroll
    for (int i = 0; i < 2; ++i)
        #pragma unroll
        for (int j = 0; j < 4; ++j)
            #pragma unroll
            for (int q = 0; q < 4; ++q) { acc_a[i][j][q] = 0.f; acc_g[i][j][q] = 0.f; }

    #pragma unroll
    for (int s = 0; s < 2; ++s) {
        uint32_t st = sb + (uint32_t)s*STAGEB;
        cpa16(st + aDst, pA + s*16);
        if (doB) cpa16(st + bDst, pB + (size_t)s*16*Ll);
        asm volatile("cp.async.commit_group;" ::: "memory");
    }

    int cur_s = 0;
    #pragma unroll 1
    for (int ks = 0; ks < 16; ++ks) {
        if (ks < 15) asm volatile("cp.async.wait_group 1;" ::: "memory");
        else         asm volatile("cp.async.wait_group 0;" ::: "memory");
        __syncthreads();
        if (ks + 2 < 16) {
            int s = ks + 2;
            int ss = cur_s + 2; if (ss >= 3) ss -= 3;
            uint32_t st = sb + (uint32_t)ss*STAGEB;
            cpa16(st + aDst, pA + s*16);
            if (doB) cpa16(st + bDst, pB + (size_t)s*16*Ll);
            asm volatile("cp.async.commit_group;" ::: "memory");
        }
        const uint32_t cur = sb + (uint32_t)cur_s*STAGEB;

        uint32_t bh[8];
        {
            uint32_t bas = cur + BOFF + b_off + (uint32_t)(wn*64);
            ldsm4t(&bh[0], bas);
            ldsm4t(&bh[4], bas + 32);
        }
        #pragma unroll
        for (int i = 0; i < 2; ++i) {
            uint32_t moff = (uint32_t)(wm*32 + i*16)*AROW + a_off;
            uint32_t aa[4], ag[4];
            ldsm4(aa, cur + 0*ABUF + moff);
            ldsm4(ag, cur + 1*ABUF + moff);
            #pragma unroll
            for (int j = 0; j < 4; ++j) {
                mma16816(acc_a[i][j], aa, bh[2*j], bh[2*j+1]);
                mma16816(acc_g[i][j], ag, bh[2*j], bh[2*j+1]);
            }
        }
        if (++cur_s == 3) cur_s = 0;
    }

    #pragma unroll
    for (int i = 0; i < 2; ++i) {
        int hr = h0 + wm*32 + i*16 + (lane >> 2);
        float ba0 = bias[hr],     bg0 = bias[Hh + hr];
        float ba1 = bias[hr + 8], bg1 = bias[Hh + hr + 8];
        #pragma unroll
        for (int j = 0; j < 4; ++j) {
            int col = l0 + wn*32 + j*8 + (lane & 3)*2;
            float a0 = acc_a[i][j][0] + ba0, g0 = acc_g[i][j][0] + bg0;
            float a1 = acc_a[i][j][1] + ba0, g1 = acc_g[i][j][1] + bg0;
            float a2 = acc_a[i][j][2] + ba1, g2 = acc_g[i][j][2] + bg1;
            float a3 = acc_a[i][j][3] + ba1, g3 = acc_g[i][j][3] + bg1;
            float2 v0 = make_float2(a0 / (1.0f + expf(-g0)),
                                    a1 / (1.0f + expf(-g1)));
            float2 v1 = make_float2(a2 / (1.0f + expf(-g2)),
                                    a3 / (1.0f + expf(-g3)));
            *(float2*)(out + ((size_t)b*Hh + hr)*Ll + col)     = v0;
            *(float2*)(out + ((size_t)b*Hh + hr + 8)*Ll + col) = v1;
        }
    }
}

// ============================================================
extern "C" void kernel_launch(void* const* d_in, const int* in_sizes, int n_in,
                              void* d_out, int out_size) {
    const float* u       = (const float*)d_in[0];
    const float* log_dt  = (const float*)d_in[1];
    const float* C       = (const float*)d_in[2];
    const float* lar     = (const float*)d_in[3];
    const float* aim     = (const float*)d_in[4];
    const float* D       = (const float*)d_in[5];
    const float* Wm      = (const float*)d_in[6];
    const float* bias    = (const float*)d_in[7];
    float* out = (float*)d_out;

    cudaFuncSetAttribute(gemm_mma_kernel,
                         cudaFuncAttributeMaxDynamicSharedMemorySize, GEMM_SMEM);

    prep_kernel<<<(Hh*N2d + 255)/256, 256>>>(log_dt, C, lar, aim);
    wsplit_kernel<<<(2*Hh*Hh + 255)/256, 256>>>(Wm);
    scan_kernel<<<(Bb*Hh/2)/4, 128>>>(u, D);
    dim3 grid(Ll/128, Hh/128, Bb);
    gemm_mma_kernel<<<grid, 512, GEMM_SMEM>>>(bias, out);
}